// round 12
// baseline (speedup 1.0000x reference)
#include <cuda_runtime.h>
#include <cuda_bf16.h>

// GaussianSplatting preprocess — FINAL (TILE=128 optimum + streaming stores):
//   out = concat(positions[N,3], cov[N,3,3], alphas[N], sh[N,4]) flattened.
//   cov = R (S S^T) R^T per point; sh = [C0, c1*C1, c0*C1, c2*C1].
// Tile-size sweep (kernel us): 512->55.8 | 256->48.9 | 128->46.8 | 64->56.0.
// v12: __stcs on all output stores (evict-first) so dirty lines retire to DRAM
// in-window instead of draining after kernel end (observed: only ~289MB of the
// 336MB mandatory traffic moves during the kernel). Kernel-time neutral per R3;
// targets the wall-vs-kernel drain gap.

#define SH_C0 0.282095f
#define SH_C1 0.488603f

constexpr int TILE = 128;

__global__ void __launch_bounds__(TILE, 16) gs_preprocess_kernel(
    const float* __restrict__ positions,  // [N,3]
    const float* __restrict__ colors,     // [N,3]
    const float* __restrict__ alphas,     // [N]
    const float* __restrict__ R,          // [N,3,3]
    const float* __restrict__ S,          // [N,3,3]
    float* __restrict__ out,              // [17N]
    int n)
{
    __shared__ float sh_col[TILE * 3];
    __shared__ float sh_R[TILE * 9];
    __shared__ float sh_S[TILE * 9];   // reused as cov staging buffer

    const int tid = threadIdx.x;
    const int block0 = blockIdx.x * TILE;

    float* __restrict__ out_cov   = out + 3LL * n;
    float* __restrict__ out_alpha = out + 12LL * n;
    float* __restrict__ out_sh    = out + 13LL * n;

    // ---------------- tiled cov + sh work ----------------
    {
        const int cnt = min(TILE, n - block0);

        if (cnt == TILE) {
            // fully coalesced float4 staging (bases: blk*12B, blk*36B -> 16B aligned)
            const float4* __restrict__ c4 = (const float4*)(colors + (long long)block0 * 3);
            const float4* __restrict__ r4 = (const float4*)(R      + (long long)block0 * 9);
            const float4* __restrict__ s4 = (const float4*)(S      + (long long)block0 * 9);
            float4* shc4 = (float4*)sh_col;
            float4* shr4 = (float4*)sh_R;
            float4* shs4 = (float4*)sh_S;
            if (tid < TILE * 3 / 4) shc4[tid] = c4[tid];          // 96 x 16B
            #pragma unroll
            for (int idx = tid; idx < TILE * 9 / 4; idx += TILE)  // 288 x 16B
                shr4[idx] = r4[idx];
            #pragma unroll
            for (int idx = tid; idx < TILE * 9 / 4; idx += TILE)
                shs4[idx] = s4[idx];
        } else {
            for (int idx = tid; idx < cnt * 3; idx += TILE)
                sh_col[idx] = colors[(long long)block0 * 3 + idx];
            for (int idx = tid; idx < cnt * 9; idx += TILE)
                sh_R[idx] = R[(long long)block0 * 9 + idx];
            for (int idx = tid; idx < cnt * 9; idx += TILE)
                sh_S[idx] = S[(long long)block0 * 9 + idx];
        }
        __syncthreads();

        if (tid < cnt) {
            const long long i = block0 + tid;

            // ---- SH coeffs (float4 streaming store when 13n is aligned) ----
            const float c0 = sh_col[tid * 3 + 0];
            const float c1 = sh_col[tid * 3 + 1];
            const float c2 = sh_col[tid * 3 + 2];
            if ((n & 3) == 0) {
                __stcs((float4*)out_sh + i,
                       make_float4(SH_C0, c1 * SH_C1, c0 * SH_C1, c2 * SH_C1));
            } else {
                out_sh[4 * i + 0] = SH_C0;
                out_sh[4 * i + 1] = c1 * SH_C1;
                out_sh[4 * i + 2] = c0 * SH_C1;
                out_sh[4 * i + 3] = c2 * SH_C1;
            }

            // ---- load r, s from smem (stride 9 -> bank-conflict-free) ----
            float r[9], s[9];
            #pragma unroll
            for (int k = 0; k < 9; ++k) r[k] = sh_R[tid * 9 + k];
            #pragma unroll
            for (int k = 0; k < 9; ++k) s[k] = sh_S[tid * 9 + k];

            // ---- M = S S^T (symmetric) ----
            const float m00 = s[0]*s[0] + s[1]*s[1] + s[2]*s[2];
            const float m01 = s[0]*s[3] + s[1]*s[4] + s[2]*s[5];
            const float m02 = s[0]*s[6] + s[1]*s[7] + s[2]*s[8];
            const float m11 = s[3]*s[3] + s[4]*s[4] + s[5]*s[5];
            const float m12 = s[3]*s[6] + s[4]*s[7] + s[5]*s[8];
            const float m22 = s[6]*s[6] + s[7]*s[7] + s[8]*s[8];

            // ---- T = R*M, cov = T*R^T; write into sh_S (own region only) ----
            float t[9];
            #pragma unroll
            for (int a = 0; a < 3; ++a) {
                const float ra0 = r[3*a + 0];
                const float ra1 = r[3*a + 1];
                const float ra2 = r[3*a + 2];
                t[3*a + 0] = ra0*m00 + ra1*m01 + ra2*m02;
                t[3*a + 1] = ra0*m01 + ra1*m11 + ra2*m12;
                t[3*a + 2] = ra0*m02 + ra1*m12 + ra2*m22;
            }
            #pragma unroll
            for (int a = 0; a < 3; ++a)
                #pragma unroll
                for (int l = 0; l < 3; ++l)
                    sh_S[tid * 9 + 3*a + l] =
                        t[3*a + 0]*r[3*l + 0] + t[3*a + 1]*r[3*l + 1] + t[3*a + 2]*r[3*l + 2];
        }
        __syncthreads();

        // ---- coalesced cov streaming store (aligned iff n%4==0) ----
        if (cnt == TILE && (n & 3) == 0) {
            float4* o4 = (float4*)(out_cov + (long long)block0 * 9);
            const float4* shs4 = (const float4*)sh_S;
            #pragma unroll
            for (int idx = tid; idx < TILE * 9 / 4; idx += TILE)
                __stcs(o4 + idx, shs4[idx]);
        } else {
            for (int idx = tid; idx < cnt * 9; idx += TILE)
                out_cov[(long long)block0 * 9 + idx] = sh_S[idx];
        }
    }

    // ---------------- flat passthrough copies (positions, alphas) ----------------
    const long long gtid    = (long long)blockIdx.x * TILE + tid;
    const long long gstride = (long long)gridDim.x * TILE;

    // positions: 3N floats
    {
        const long long nv = (3LL * n) >> 2;
        const float4* p4 = (const float4*)positions;
        float4* o4 = (float4*)out;
        for (long long idx = gtid; idx < nv; idx += gstride)
            __stcs(o4 + idx, p4[idx]);
        for (long long idx = nv * 4 + gtid; idx < 3LL * n; idx += gstride)
            out[idx] = positions[idx];
    }
    // alphas: N floats (dst base 48n B -> always 16B aligned)
    {
        const long long nv = (long long)n >> 2;
        const float4* a4 = (const float4*)alphas;
        float4* o4 = (float4*)out_alpha;
        for (long long idx = gtid; idx < nv; idx += gstride)
            __stcs(o4 + idx, a4[idx]);
        for (long long idx = nv * 4 + gtid; idx < n; idx += gstride)
            out_alpha[idx] = alphas[idx];
    }
}

extern "C" void kernel_launch(void* const* d_in, const int* in_sizes, int n_in,
                              void* d_out, int out_size)
{
    const float* positions = (const float*)d_in[0];
    const float* colors    = (const float*)d_in[1];
    const float* alphas    = (const float*)d_in[2];
    const float* R         = (const float*)d_in[3];
    const float* S         = (const float*)d_in[4];
    float* out = (float*)d_out;

    const int n = in_sizes[2];  // alphas count == N

    const int blocks = (n + TILE - 1) / TILE;
    gs_preprocess_kernel<<<blocks, TILE>>>(positions, colors, alphas, R, S, out, n);
}

// round 13
// speedup vs baseline: 1.0137x; 1.0137x over previous
#include <cuda_runtime.h>
#include <cuda_bf16.h>

// GaussianSplatting preprocess — FINAL CHAMPION (TILE=128, default stores):
//   out = concat(positions[N,3], cov[N,3,3], alphas[N], sh[N,4]) flattened.
//   cov = R (S S^T) R^T per point; sh = [C0, c1*C1, c0*C1, c2*C1].
// Full design-space map (kernel us / DRAM%):
//   scalar 75.7/49 | cp.async 48.9/74 | T512 55.8/66 | reorder 54.0/68 |
//   warp-auto 49.9/75 | T256 48.9/74 | T64 56.0/67 | stcs 51.1/71 |
//   THIS (T128, default stores) 46.8-47.5 / 76-77  <- optimum, verified 3x.
// HBM-bound at ~6.1 TB/s (mixed r/w ceiling); 336MB mandatory traffic.
// All global traffic float4-coalesced via smem staging; default store policy
// (evict-normal) deliberately kept: L2 write-drain overlap beats eager stcs.

#define SH_C0 0.282095f
#define SH_C1 0.488603f

constexpr int TILE = 128;

__global__ void __launch_bounds__(TILE, 16) gs_preprocess_kernel(
    const float* __restrict__ positions,  // [N,3]
    const float* __restrict__ colors,     // [N,3]
    const float* __restrict__ alphas,     // [N]
    const float* __restrict__ R,          // [N,3,3]
    const float* __restrict__ S,          // [N,3,3]
    float* __restrict__ out,              // [17N]
    int n)
{
    __shared__ float sh_col[TILE * 3];
    __shared__ float sh_R[TILE * 9];
    __shared__ float sh_S[TILE * 9];   // reused as cov staging buffer

    const int tid = threadIdx.x;
    const int block0 = blockIdx.x * TILE;

    float* __restrict__ out_cov   = out + 3LL * n;
    float* __restrict__ out_alpha = out + 12LL * n;
    float* __restrict__ out_sh    = out + 13LL * n;

    // ---------------- tiled cov + sh work ----------------
    {
        const int cnt = min(TILE, n - block0);

        if (cnt == TILE) {
            // fully coalesced float4 staging (bases: blk*12B, blk*36B -> 16B aligned)
            const float4* __restrict__ c4 = (const float4*)(colors + (long long)block0 * 3);
            const float4* __restrict__ r4 = (const float4*)(R      + (long long)block0 * 9);
            const float4* __restrict__ s4 = (const float4*)(S      + (long long)block0 * 9);
            float4* shc4 = (float4*)sh_col;
            float4* shr4 = (float4*)sh_R;
            float4* shs4 = (float4*)sh_S;
            if (tid < TILE * 3 / 4) shc4[tid] = c4[tid];          // 96 x 16B
            #pragma unroll
            for (int idx = tid; idx < TILE * 9 / 4; idx += TILE)  // 288 x 16B
                shr4[idx] = r4[idx];
            #pragma unroll
            for (int idx = tid; idx < TILE * 9 / 4; idx += TILE)
                shs4[idx] = s4[idx];
        } else {
            for (int idx = tid; idx < cnt * 3; idx += TILE)
                sh_col[idx] = colors[(long long)block0 * 3 + idx];
            for (int idx = tid; idx < cnt * 9; idx += TILE)
                sh_R[idx] = R[(long long)block0 * 9 + idx];
            for (int idx = tid; idx < cnt * 9; idx += TILE)
                sh_S[idx] = S[(long long)block0 * 9 + idx];
        }
        __syncthreads();

        if (tid < cnt) {
            const long long i = block0 + tid;

            // ---- SH coeffs (direct float4 store when 13n is float4-aligned) ----
            const float c0 = sh_col[tid * 3 + 0];
            const float c1 = sh_col[tid * 3 + 1];
            const float c2 = sh_col[tid * 3 + 2];
            if ((n & 3) == 0) {
                ((float4*)out_sh)[i] =
                    make_float4(SH_C0, c1 * SH_C1, c0 * SH_C1, c2 * SH_C1);
            } else {
                out_sh[4 * i + 0] = SH_C0;
                out_sh[4 * i + 1] = c1 * SH_C1;
                out_sh[4 * i + 2] = c0 * SH_C1;
                out_sh[4 * i + 3] = c2 * SH_C1;
            }

            // ---- load r, s from smem (stride 9 -> bank-conflict-free) ----
            float r[9], s[9];
            #pragma unroll
            for (int k = 0; k < 9; ++k) r[k] = sh_R[tid * 9 + k];
            #pragma unroll
            for (int k = 0; k < 9; ++k) s[k] = sh_S[tid * 9 + k];

            // ---- M = S S^T (symmetric) ----
            const float m00 = s[0]*s[0] + s[1]*s[1] + s[2]*s[2];
            const float m01 = s[0]*s[3] + s[1]*s[4] + s[2]*s[5];
            const float m02 = s[0]*s[6] + s[1]*s[7] + s[2]*s[8];
            const float m11 = s[3]*s[3] + s[4]*s[4] + s[5]*s[5];
            const float m12 = s[3]*s[6] + s[4]*s[7] + s[5]*s[8];
            const float m22 = s[6]*s[6] + s[7]*s[7] + s[8]*s[8];

            // ---- T = R*M, cov = T*R^T; write into sh_S (own region only) ----
            float t[9];
            #pragma unroll
            for (int a = 0; a < 3; ++a) {
                const float ra0 = r[3*a + 0];
                const float ra1 = r[3*a + 1];
                const float ra2 = r[3*a + 2];
                t[3*a + 0] = ra0*m00 + ra1*m01 + ra2*m02;
                t[3*a + 1] = ra0*m01 + ra1*m11 + ra2*m12;
                t[3*a + 2] = ra0*m02 + ra1*m12 + ra2*m22;
            }
            #pragma unroll
            for (int a = 0; a < 3; ++a)
                #pragma unroll
                for (int l = 0; l < 3; ++l)
                    sh_S[tid * 9 + 3*a + l] =
                        t[3*a + 0]*r[3*l + 0] + t[3*a + 1]*r[3*l + 1] + t[3*a + 2]*r[3*l + 2];
        }
        __syncthreads();

        // ---- coalesced cov store (base: 3n + blk*9 floats; aligned iff n%4==0) ----
        if (cnt == TILE && (n & 3) == 0) {
            float4* o4 = (float4*)(out_cov + (long long)block0 * 9);
            const float4* shs4 = (const float4*)sh_S;
            #pragma unroll
            for (int idx = tid; idx < TILE * 9 / 4; idx += TILE)
                o4[idx] = shs4[idx];
        } else {
            for (int idx = tid; idx < cnt * 9; idx += TILE)
                out_cov[(long long)block0 * 9 + idx] = sh_S[idx];
        }
    }

    // ---------------- flat passthrough copies (positions, alphas) ----------------
    const long long gtid    = (long long)blockIdx.x * TILE + tid;
    const long long gstride = (long long)gridDim.x * TILE;

    // positions: 3N floats
    {
        const long long nv = (3LL * n) >> 2;
        const float4* p4 = (const float4*)positions;
        float4* o4 = (float4*)out;
        for (long long idx = gtid; idx < nv; idx += gstride) o4[idx] = p4[idx];
        for (long long idx = nv * 4 + gtid; idx < 3LL * n; idx += gstride)
            out[idx] = positions[idx];
    }
    // alphas: N floats (dst base 48n B -> always 16B aligned)
    {
        const long long nv = (long long)n >> 2;
        const float4* a4 = (const float4*)alphas;
        float4* o4 = (float4*)out_alpha;
        for (long long idx = gtid; idx < nv; idx += gstride) o4[idx] = a4[idx];
        for (long long idx = nv * 4 + gtid; idx < n; idx += gstride)
            out_alpha[idx] = alphas[idx];
    }
}

extern "C" void kernel_launch(void* const* d_in, const int* in_sizes, int n_in,
                              void* d_out, int out_size)
{
    const float* positions = (const float*)d_in[0];
    const float* colors    = (const float*)d_in[1];
    const float* alphas    = (const float*)d_in[2];
    const float* R         = (const float*)d_in[3];
    const float* S         = (const float*)d_in[4];
    float* out = (float*)d_out;

    const int n = in_sizes[2];  // alphas count == N

    const int blocks = (n + TILE - 1) / TILE;
    gs_preprocess_kernel<<<blocks, TILE>>>(positions, colors, alphas, R, S, out, n);
}